// round 16
// baseline (speedup 1.0000x reference)
#include <cuda_runtime.h>
#include <cuda_fp16.h>
#include <cstdint>

// Problem constants
#define CB 4
#define CT 2048
#define CD 2048
#define CH 16
#define CHD 128
#define QKVD (3 * CD)   // 6144

// Scratch (allocation-free rule: __device__ globals)
__device__ __half g_qkv[(size_t)CB * CT * QKVD];   // fp16 qkv
__device__ __half g_y[(size_t)CB * CT * CD];       // fp16 attention output
__device__ __half g_xh[(size_t)CB * CT * CD];      // x in fp16
__device__ __half g_wqkvh[(size_t)QKVD * CD];      // w_qkv in fp16
__device__ __half g_woh[(size_t)CD * CD];          // w_o in fp16

__device__ __forceinline__ float ex2(float x) {
    float r;
    asm("ex2.approx.f32 %0, %1;" : "=f"(r) : "f"(x));
    return r;
}

__device__ __forceinline__ void mma_f16(
    float& c0, float& c1, float& c2, float& c3,
    uint32_t a0, uint32_t a1, uint32_t a2, uint32_t a3,
    uint32_t b0, uint32_t b1)
{
    asm volatile(
        "mma.sync.aligned.m16n8k16.row.col.f32.f16.f16.f32 "
        "{%0,%1,%2,%3}, {%4,%5,%6,%7}, {%8,%9}, {%0,%1,%2,%3};"
        : "+f"(c0), "+f"(c1), "+f"(c2), "+f"(c3)
        : "r"(a0), "r"(a1), "r"(a2), "r"(a3), "r"(b0), "r"(b1));
}

__device__ __forceinline__ void ldsm_x4(
    uint32_t& r0, uint32_t& r1, uint32_t& r2, uint32_t& r3, uint32_t addr)
{
    asm volatile(
        "ldmatrix.sync.aligned.m8n8.x4.shared.b16 {%0,%1,%2,%3}, [%4];"
        : "=r"(r0), "=r"(r1), "=r"(r2), "=r"(r3) : "r"(addr));
}
__device__ __forceinline__ void ldsm_x4_trans(
    uint32_t& r0, uint32_t& r1, uint32_t& r2, uint32_t& r3, uint32_t addr)
{
    asm volatile(
        "ldmatrix.sync.aligned.m8n8.x4.trans.shared.b16 {%0,%1,%2,%3}, [%4];"
        : "=r"(r0), "=r"(r1), "=r"(r2), "=r"(r3) : "r"(addr));
}

__device__ __forceinline__ void cp16(uint32_t smem, const void* gmem) {
    asm volatile("cp.async.cg.shared.global [%0], [%1], 16;"
                 :: "r"(smem), "l"(gmem));
}
__device__ __forceinline__ void cp_commit() {
    asm volatile("cp.async.commit_group;");
}
template <int N>
__device__ __forceinline__ void cp_wait() {
    asm volatile("cp.async.wait_group %0;" :: "n"(N));
}

// Byte offsets for b16 ldmatrix lanes. Strides in HALVES.
__device__ __forceinline__ uint32_t a_off16(int l, int sh) {
    return (uint32_t)((((l & 7) + ((l >> 3) & 1) * 8) * sh + (l >> 4) * 8) * 2);
}
__device__ __forceinline__ uint32_t b_off16(int l, int sh) {
    return (uint32_t)(((((l >> 4) & 1) * 8 + (l & 7)) * sh + ((l >> 3) & 1) * 8) * 2);
}

// ---------------------------------------------------------------------------
// Elementwise fp32 -> fp16 conversion
// ---------------------------------------------------------------------------
__global__ __launch_bounds__(256) void f32_to_f16_kernel(
    const float4* __restrict__ in, __half2* __restrict__ out, int n4)
{
    int i = blockIdx.x * blockDim.x + threadIdx.x;
    if (i < n4) {
        float4 v = in[i];
        out[2 * i]     = __floats2half2_rn(v.x, v.y);
        out[2 * i + 1] = __floats2half2_rn(v.z, v.w);
    }
}

// ===========================================================================
// fp16 tensor-core NT GEMM: C[M,N] = A[M,K] @ B[N,K]^T, A/B fp16 in gmem.
// CTA tile 128x128, BK=64, 256 threads = 8 warps (2m x 4n), warp tile 64x32.
// 3-stage cp.async ring, one sync per stage. TWO CTAs per SM so that one
// CTA's MMA stream covers the other CTA's stage-boundary stalls.
// ===========================================================================
#define SAST 72                      // halves per smem row (64 + 8 pad)
#define A_BUF_H (128 * SAST)         // 9216 halves
#define B_BUF_H (128 * SAST)         // 9216 halves
#define GNST 3
#define SGEMM_SMEM_BYTES ((GNST * (A_BUF_H + B_BUF_H)) * 2)   // 110592
#define GTHREADS 256

__global__ __launch_bounds__(GTHREADS, 2) void hgemm_tc(
    const __half* __restrict__ A, const __half* __restrict__ Bm,
    float* __restrict__ Cf, __half* __restrict__ Ch,
    int M, int N, int K, int outHalf)
{
    extern __shared__ __half smh[];
    const uint32_t aSm = (uint32_t)__cvta_generic_to_shared(smh);
    const uint32_t bSm = aSm + (uint32_t)(GNST * A_BUF_H * 2);

    const int tid = threadIdx.x;
    const int wid = tid >> 5;             // 0..7
    const int lane = tid & 31;
    const int g = lane >> 2;
    const int q = lane & 3;

    const int warp_m = wid & 1;           // 0..1 -> m offset *64
    const int warp_n = wid >> 1;          // 0..3 -> n offset *32

    const int rowBase = blockIdx.y * 128;
    const int colBase = blockIdx.x * 128;

    // cp.async mapping: row chunk = 8 halves; 8 chunks per 64-half row.
    const int arow = tid >> 3;            // 0..31
    const int ac = (tid & 7) * 8;         // halves 0..56
    const __half* Asrc = A + (size_t)(rowBase + arow) * K + ac;
    const __half* Bsrc = Bm + (size_t)(colBase + arow) * K + ac;
    const uint32_t dDst = (uint32_t)((arow * SAST + ac) * 2);

    const uint32_t aFrag0 = aSm + a_off16(lane, SAST)
                          + (uint32_t)(warp_m * 64 * SAST * 2);
    const uint32_t bFrag0 = bSm + b_off16(lane, SAST)
                          + (uint32_t)(warp_n * 32 * SAST * 2);

    float acc[4][4][4];   // [mt][nt][c] : warp tile 64(m) x 32(n)
#pragma unroll
    for (int mt = 0; mt < 4; mt++)
#pragma unroll
        for (int nt = 0; nt < 4; nt++)
#pragma unroll
            for (int c = 0; c < 4; c++) acc[mt][nt][c] = 0.0f;

    const int nstages = K >> 6;   // K/64 = 32

    auto issue = [&](int st) {
        const int koff = st << 6;
        const int buf = st % GNST;
        const uint32_t aB = aSm + (uint32_t)(buf * A_BUF_H * 2) + dDst;
        const uint32_t bB = bSm + (uint32_t)(buf * B_BUF_H * 2) + dDst;
#pragma unroll
        for (int p = 0; p < 4; p++)
            cp16(aB + (uint32_t)(p * 32 * SAST * 2),
                 Asrc + (size_t)(p * 32) * K + koff);
#pragma unroll
        for (int p = 0; p < 4; p++)
            cp16(bB + (uint32_t)(p * 32 * SAST * 2),
                 Bsrc + (size_t)(p * 32) * K + koff);
        cp_commit();
    };

    issue(0); issue(1);

    for (int s = 0; s < nstages; s++) {
        if (s < nstages - 1) cp_wait<1>();
        else                 cp_wait<0>();
        __syncthreads();
        // Refill buffer (s+2)%3 == (s-1)%3: stage s-1's consumers finished
        // before every thread passed the sync above.
        if (s + 2 < nstages) issue(s + 2);

        const int buf = s % GNST;
        const uint32_t aOff = (uint32_t)(buf * A_BUF_H * 2);
        const uint32_t bOff = (uint32_t)(buf * B_BUF_H * 2);

#pragma unroll
        for (int ks = 0; ks < 4; ks++) {
            const uint32_t kkB = (uint32_t)(ks * 16 * 2);
            uint32_t afr[4][4];
#pragma unroll
            for (int mt = 0; mt < 4; mt++)
                ldsm_x4(afr[mt][0], afr[mt][1], afr[mt][2], afr[mt][3],
                        aFrag0 + aOff + (uint32_t)((mt * 16 * SAST) * 2) + kkB);
#pragma unroll
            for (int ntp = 0; ntp < 2; ntp++) {
                uint32_t b0, b1, b2, b3;
                ldsm_x4(b0, b1, b2, b3,
                        bFrag0 + bOff + (uint32_t)((ntp * 16 * SAST) * 2) + kkB);
#pragma unroll
                for (int mt = 0; mt < 4; mt++) {
                    mma_f16(acc[mt][2 * ntp][0], acc[mt][2 * ntp][1],
                            acc[mt][2 * ntp][2], acc[mt][2 * ntp][3],
                            afr[mt][0], afr[mt][1], afr[mt][2], afr[mt][3],
                            b0, b1);
                    mma_f16(acc[mt][2 * ntp + 1][0], acc[mt][2 * ntp + 1][1],
                            acc[mt][2 * ntp + 1][2], acc[mt][2 * ntp + 1][3],
                            afr[mt][0], afr[mt][1], afr[mt][2], afr[mt][3],
                            b2, b3);
                }
            }
        }
    }

    // Epilogue: warp tile 64x32
#pragma unroll
    for (int mt = 0; mt < 4; mt++) {
        const int m0 = rowBase + warp_m * 64 + mt * 16;
#pragma unroll
        for (int nt = 0; nt < 4; nt++) {
            const int n0 = colBase + warp_n * 32 + nt * 8;
            if (outHalf) {
                *(__half2*)(Ch + (size_t)(m0 + g) * N + n0 + 2 * q) =
                    __floats2half2_rn(acc[mt][nt][0], acc[mt][nt][1]);
                *(__half2*)(Ch + (size_t)(m0 + g + 8) * N + n0 + 2 * q) =
                    __floats2half2_rn(acc[mt][nt][2], acc[mt][nt][3]);
            } else {
                *(float2*)(Cf + (size_t)(m0 + g) * N + n0 + 2 * q) =
                    make_float2(acc[mt][nt][0], acc[mt][nt][1]);
                *(float2*)(Cf + (size_t)(m0 + g + 8) * N + n0 + 2 * q) =
                    make_float2(acc[mt][nt][2], acc[mt][nt][3]);
            }
        }
    }
}

// ===========================================================================
// fp16 tensor-core flash attention (unchanged from R15).
// ===========================================================================
#define FQ 128
#define FKT 64
#define QSTH 136
#define PSTH 72
#define KVBUF (FKT * QSTH)

#define FLASH_SMEM_BYTES ((FQ * QSTH + 4 * KVBUF + FQ * PSTH) * 2 + 2 * FKT * 4)

__global__ __launch_bounds__(256, 1) void flash_attn_f16(
    const __half* __restrict__ qkv, const int* __restrict__ mask,
    __half* __restrict__ y)
{
    extern __shared__ __half smh[];
    __half* Qs = smh;                          // FQ x QSTH
    __half* Ks = Qs + FQ * QSTH;               // 2 x KVBUF
    __half* Vs = Ks + 2 * KVBUF;               // 2 x KVBUF
    __half* Ps = Vs + 2 * KVBUF;               // FQ x PSTH
    float* bias = (float*)(Ps + FQ * PSTH);    // [2][FKT]

    const int qt = blockIdx.x;
    const int bh = blockIdx.y;
    const int b = bh / CH;
    const int h = bh % CH;

    const int tid = threadIdx.x;
    const int wid = tid >> 5;
    const int lane = tid & 31;
    const int g = lane >> 2;
    const int q = lane & 3;
    const int m0 = wid * 16;

    const size_t baseQ = (size_t)b * CT * QKVD + (size_t)h * CHD;
    const size_t baseK = baseQ + CD;
    const size_t baseV = baseQ + 2 * CD;
    const int q0 = qt * FQ;

    const uint32_t qSm = (uint32_t)__cvta_generic_to_shared(Qs);
    const uint32_t kSm = (uint32_t)__cvta_generic_to_shared(Ks);
    const uint32_t vSm = (uint32_t)__cvta_generic_to_shared(Vs);
    const uint32_t pSm = (uint32_t)__cvta_generic_to_shared(Ps);

    const uint32_t aQ = qSm + a_off16(lane, QSTH) + (uint32_t)(m0 * QSTH * 2);
    const uint32_t bK = kSm + b_off16(lane, QSTH);
    const uint32_t aP = pSm + a_off16(lane, PSTH) + (uint32_t)(m0 * PSTH * 2);
    const uint32_t tV = vSm + a_off16(lane, QSTH);

    const int krow = tid >> 4;            // 0..15
    const int kc = (tid & 15) * 8;        // halves

    // Q tile
    {
#pragma unroll
        for (int p = 0; p < 8; p++) {
            int r = krow + p * 16;
            cp16(qSm + (uint32_t)((r * QSTH + kc) * 2),
                 qkv + baseQ + (size_t)(q0 + r) * QKVD + kc);
        }
        cp_commit();
    }

    auto issueKV = [&](int ti) {
        const int kt0 = ti * FKT;
        const int buf = ti & 1;
        const uint32_t kB = kSm + (uint32_t)(buf * KVBUF * 2);
        const uint32_t vB = vSm + (uint32_t)(buf * KVBUF * 2);
#pragma unroll
        for (int p = 0; p < 4; p++) {
            int r = krow + p * 16;
            cp16(kB + (uint32_t)((r * QSTH + kc) * 2),
                 qkv + baseK + (size_t)(kt0 + r) * QKVD + kc);
            cp16(vB + (uint32_t)((r * QSTH + kc) * 2),
                 qkv + baseV + (size_t)(kt0 + r) * QKVD + kc);
        }
        if (tid < FKT)
            bias[buf * FKT + tid] = mask[b * CT + kt0 + tid] ? 0.0f : -1e30f;
        cp_commit();
    };

    issueKV(0);

    float acc[16][4];
#pragma unroll
    for (int nt = 0; nt < 16; nt++)
#pragma unroll
        for (int c = 0; c < 4; c++) acc[nt][c] = 0.0f;
    float m_r0 = -1e30f, m_r1 = -1e30f;
    float l_r0 = 0.0f, l_r1 = 0.0f;

    const float cs = 0.08838834764831845f * 1.4426950408889634f;
    const int ntiles = CT / FKT;

    for (int ti = 0; ti < ntiles; ti++) {
        cp_wait<0>();
        __syncthreads();
        if (ti + 1 < ntiles) issueKV(ti + 1);

        const int buf = ti & 1;
        const uint32_t kOff = (uint32_t)(buf * KVBUF * 2);
        const float* bb = bias + buf * FKT;

        // ---- S = Q @ K^T ----
        float s[8][4];
#pragma unroll
        for (int nt = 0; nt < 8; nt++)
#pragma unroll
            for (int c = 0; c < 4; c++) s[nt][c] = 0.0f;

#pragma unroll
        for (int ks = 0; ks < 8; ks++) {
            const uint32_t kkB = (uint32_t)(ks * 16 * 2);
            uint32_t a0, a1, a2, a3;
            ldsm_x4(a0, a1, a2, a3, aQ + kkB);
#pragma unroll
            for (int ntp = 0; ntp < 4; ntp++) {
                uint32_t b0, b1, b2, b3;
                ldsm_x4(b0, b1, b2, b3,
                        bK + kOff + (uint32_t)(ntp * 16 * QSTH * 2) + kkB);
                mma_f16(s[2 * ntp][0], s[2 * ntp][1],
                        s[2 * ntp][2], s[2 * ntp][3],
                        a0, a1, a2, a3, b0, b1);
                mma_f16(s[2 * ntp + 1][0], s[2 * ntp + 1][1],
                        s[2 * ntp + 1][2], s[2 * ntp + 1][3],
                        a0, a1, a2, a3, b2, b3);
            }
        }

#pragma unroll
        for (int nt = 0; nt < 8; nt++) {
            float2 bv = *(const float2*)&bb[nt * 8 + 2 * q];
            s[nt][0] = fmaf(s[nt][0], cs, bv.x);
            s[nt][1] = fmaf(s[nt][1], cs, bv.y);
            s[nt][2] = fmaf(s[nt][2], cs, bv.x);
            s[nt][3] = fmaf(s[nt][3], cs, bv.y);
        }

        float tm0 = -1e30f, tm1 = -1e30f;
#pragma unroll
        for (int nt = 0; nt < 8; nt++) {
            tm0 = fmaxf(tm0, fmaxf(s[nt][0], s[nt][1]));
            tm1 = fmaxf(tm1, fmaxf(s[nt][2], s[nt][3]));
        }
        tm0 = fmaxf(tm0, __shfl_xor_sync(0xffffffffu, tm0, 1));
        tm0 = fmaxf(tm0, __shfl_xor_sync(0xffffffffu, tm0, 2));
        tm1 = fmaxf(tm1, __shfl_xor_sync(0xffffffffu, tm1, 1));
        tm1 = fmaxf(tm1, __shfl_xor_sync(0xffffffffu, tm1, 2));

        const float mn0 = fmaxf(m_r0, tm0);
        const float mn1 = fmaxf(m_r1, tm1);
        const float corr0 = ex2(m_r0 - mn0);
        const float corr1 = ex2(m_r1 - mn1);
        m_r0 = mn0; m_r1 = mn1;

        float ps0 = 0.0f, ps1 = 0.0f;
#pragma unroll
        for (int nt = 0; nt < 8; nt++) {
            float p0 = ex2(s[nt][0] - mn0);
            float p1 = ex2(s[nt][1] - mn0);
            float p2 = ex2(s[nt][2] - mn1);
            float p3 = ex2(s[nt][3] - mn1);
            ps0 += p0 + p1;
            ps1 += p2 + p3;
            *(__half2*)&Ps[(m0 + g) * PSTH + nt * 8 + 2 * q] =
                __floats2half2_rn(p0, p1);
            *(__half2*)&Ps[(m0 + g + 8) * PSTH + nt * 8 + 2 * q] =
                __floats2half2_rn(p2, p3);
        }
        ps0 += __shfl_xor_sync(0xffffffffu, ps0, 1);
        ps0 += __shfl_xor_sync(0xffffffffu, ps0, 2);
        ps1 += __shfl_xor_sync(0xffffffffu, ps1, 1);
        ps1 += __shfl_xor_sync(0xffffffffu, ps1, 2);
        l_r0 = l_r0 * corr0 + ps0;
        l_r1 = l_r1 * corr1 + ps1;

#pragma unroll
        for (int nt = 0; nt < 16; nt++) {
            acc[nt][0] *= corr0; acc[nt][1] *= corr0;
            acc[nt][2] *= corr1; acc[nt][3] *= corr1;
        }
        __syncwarp();

        // ---- O += P @ V ----
#pragma unroll
        for (int ks = 0; ks < 4; ks++) {
            uint32_t a0, a1, a2, a3;
            ldsm_x4(a0, a1, a2, a3, aP + (uint32_t)(ks * 16 * 2));
#pragma unroll
            for (int ntp = 0; ntp < 8; ntp++) {
                uint32_t b0, b1, b2, b3;
                ldsm_x4_trans(b0, b1, b2, b3,
                              tV + kOff
                              + (uint32_t)((ks * 16 * QSTH + ntp * 16) * 2));
                mma_f16(acc[2 * ntp][0], acc[2 * ntp][1],
                        acc[2 * ntp][2], acc[2 * ntp][3],
                        a0, a1, a2, a3, b0, b1);
                mma_f16(acc[2 * ntp + 1][0], acc[2 * ntp + 1][1],
                        acc[2 * ntp + 1][2], acc[2 * ntp + 1][3],
                        a0, a1, a2, a3, b2, b3);
            }
        }
    }

    const float inv0 = 1.0f / l_r0;
    const float inv1 = 1.0f / l_r1;
    const int row0 = q0 + m0 + g;
    const int row1 = row0 + 8;
    __half* y0 = y + (size_t)(b * CT + row0) * CD + h * CHD;
    __half* y1 = y + (size_t)(b * CT + row1) * CD + h * CHD;
#pragma unroll
    for (int nt = 0; nt < 16; nt++) {
        const int col = nt * 8 + 2 * q;
        *(__half2*)(y0 + col) =
            __floats2half2_rn(acc[nt][0] * inv0, acc[nt][1] * inv0);
        *(__half2*)(y1 + col) =
            __floats2half2_rn(acc[nt][2] * inv1, acc[nt][3] * inv1);
    }
}

// ---------------------------------------------------------------------------
extern "C" void kernel_launch(void* const* d_in, const int* in_sizes, int n_in,
                              void* d_out, int out_size)
{
    const float* x      = (const float*)d_in[0];
    const int*   mask   = (const int*)d_in[1];
    const float* w_qkv  = (const float*)d_in[2];
    const float* w_o    = (const float*)d_in[3];
    float*       out    = (float*)d_out;

    __half *qkv = nullptr, *y = nullptr, *xh = nullptr, *wqkvh = nullptr, *woh = nullptr;
    cudaGetSymbolAddress((void**)&qkv, g_qkv);
    cudaGetSymbolAddress((void**)&y, g_y);
    cudaGetSymbolAddress((void**)&xh, g_xh);
    cudaGetSymbolAddress((void**)&wqkvh, g_wqkvh);
    cudaGetSymbolAddress((void**)&woh, g_woh);

    cudaFuncSetAttribute(hgemm_tc,
                         cudaFuncAttributeMaxDynamicSharedMemorySize,
                         SGEMM_SMEM_BYTES);
    cudaFuncSetAttribute(flash_attn_f16,
                         cudaFuncAttributeMaxDynamicSharedMemorySize,
                         FLASH_SMEM_BYTES);

    // 0) Convert inputs to fp16
    {
        int n4x = (CB * CT * CD) / 4;
        int n4w = (QKVD * CD) / 4;
        int n4o = (CD * CD) / 4;
        f32_to_f16_kernel<<<(n4x + 255) / 256, 256>>>((const float4*)x, (__half2*)xh, n4x);
        f32_to_f16_kernel<<<(n4w + 255) / 256, 256>>>((const float4*)w_qkv, (__half2*)wqkvh, n4w);
        f32_to_f16_kernel<<<(n4o + 255) / 256, 256>>>((const float4*)w_o, (__half2*)woh, n4o);
    }

    // 1) qkv = xh @ wqkvh^T : M=8192, N=6144, K=2048 (fp16 out)
    {
        dim3 grid(QKVD / 128, (CB * CT) / 128);
        hgemm_tc<<<grid, GTHREADS, SGEMM_SMEM_BYTES>>>(
            xh, wqkvh, nullptr, qkv, CB * CT, QKVD, CD, 1);
    }

    // 2) fused attention -> y (fp16)
    {
        dim3 grid(CT / FQ, CB * CH);
        flash_attn_f16<<<grid, 256, FLASH_SMEM_BYTES>>>(qkv, mask, y);
    }

    // 3) out = y @ woh^T : M=8192, N=2048, K=2048 (fp32 out)
    {
        dim3 grid(CD / 128, (CB * CT) / 128);
        hgemm_tc<<<grid, GTHREADS, SGEMM_SMEM_BYTES>>>(
            y, woh, out, nullptr, CB * CT, CD, CD, 0);
    }
}